// round 11
// baseline (speedup 1.0000x reference)
#include <cuda_runtime.h>

// Problem constants
#define Nn 1024   // nodes (== hidden_dim)
#define Tt 32     // seq len
#define Dd 256    // state dim
#define Hh 1024   // hidden dim
#define Ee 64     // action logits
#define DH (Dd + Hh)   // 1280

// ---------------- scratch: __device__ globals, referenced ONLY from kernels
__device__ float g_WZR[DH * 2 * Hh];   // [Wz@adj | Wr@adj]  (1280 x 2048)
__device__ float g_WC [DH * Hh];       // Wh@adj             (1280 x 1024)
__device__ float g_h  [Nn * Hh];       // hidden state h_t
__device__ float g_z  [Nn * Hh];       // update gate z
__device__ float g_rh [Nn * Hh];       // r * h
__device__ float g_bzr[2 * Hh];        // packed [bz | br]

__device__ __forceinline__ float sigm(float x) { return 1.0f / (1.0f + expf(-x)); }

// ---------------- textbook 32x32 tiled GEMM: dst = W[1280,1024] @ adj ------
// DST 0: g_WZR cols [0,1024)    (ldc 2048)
// DST 1: g_WZR cols [1024,2048) (ldc 2048)
// DST 2: g_WC                   (ldc 1024)
template <int DST>
__global__ void __launch_bounds__(1024)
fold_k(const float* __restrict__ A, const float* __restrict__ B)
{
    __shared__ float As[32][33];
    __shared__ float Bs[32][33];
    const int tx = threadIdx.x, ty = threadIdx.y;
    const int row = blockIdx.y * 32 + ty;    // [0,1280)
    const int col = blockIdx.x * 32 + tx;    // [0,1024)

    float acc = 0.f;
    for (int k0 = 0; k0 < Hh; k0 += 32) {
        As[ty][tx] = A[row * Hh + k0 + tx];          // W row-major, lda=1024
        Bs[ty][tx] = B[(k0 + ty) * Nn + col];        // adj row-major, ldb=1024
        __syncthreads();
#pragma unroll
        for (int kk = 0; kk < 32; kk++) acc += As[ty][kk] * Bs[kk][tx];
        __syncthreads();
    }
    if (DST == 0)      g_WZR[row * 2 * Hh + col]      = acc;
    else if (DST == 1) g_WZR[row * 2 * Hh + Hh + col] = acc;
    else               g_WC [row * Hh + col]          = acc;
}

// ---------------- recurrent step GEMMs, A = [x_t | state], K = 1280 --------
// EPI 0 (gates): B = g_WZR (N=2048), state = g_h, bias = g_bzr
//    col <  H:  g_z [row,col]   = sigmoid(acc + bz[col])
//    col >= H:  g_rh[row,col-H] = sigmoid(acc + br[col-H]) * g_h[row,col-H]
// EPI 1 (cand):  B = g_WC (N=1024), state = g_rh, bias = bh (input ptr)
//    g_h = sigmoid(z*h + (1-z)*tanh(acc + bh[col]))
template <int EPI>
__global__ void __launch_bounds__(1024)
step_k(const float* __restrict__ x, int t,
       const float* __restrict__ bias)
{
    __shared__ float As[32][33];
    __shared__ float Bs[32][33];
    const int tx = threadIdx.x, ty = threadIdx.y;
    const int row = blockIdx.y * 32 + ty;     // node, [0,1024)
    const int col = blockIdx.x * 32 + tx;     // [0,2048) EPI0 / [0,1024) EPI1

    const float* state = (EPI == 0) ? g_h : g_rh;
    const float* W     = (EPI == 0) ? g_WZR : g_WC;
    const int    ldb   = (EPI == 0) ? 2 * Hh : Hh;

    float acc = 0.f;
    for (int k0 = 0; k0 < DH; k0 += 32) {
        const int k = k0 + tx;
        As[ty][tx] = (k < Dd) ? x[row * (Tt * Dd) + t * Dd + k]
                              : state[row * Hh + (k - Dd)];
        Bs[ty][tx] = W[(k0 + ty) * ldb + col];
        __syncthreads();
#pragma unroll
        for (int kk = 0; kk < 32; kk++) acc += As[ty][kk] * Bs[kk][tx];
        __syncthreads();
    }

    if (EPI == 0) {
        if (col < Hh) {
            g_z[row * Hh + col] = sigm(acc + g_bzr[col]);
        } else {
            const int c = col - Hh;
            g_rh[row * Hh + c] = g_h[row * Hh + c] * sigm(acc + g_bzr[Hh + c]);
        }
    } else {
        const int idx = row * Hh + col;
        const float ht = tanhf(acc + bias[col]);
        const float z  = g_z[idx];
        const float h  = g_h[idx];
        g_h[idx] = sigm(z * h + (1.0f - z) * ht);
    }
}

__global__ void __launch_bounds__(256)
pack_bias_k(const float* __restrict__ bz, const float* __restrict__ br)
{
    const int i = blockIdx.x * blockDim.x + threadIdx.x;   // [0, 2H)
    g_bzr[i] = (i < Hh) ? bz[i] : br[i - Hh];
}

// ---------------- fc + argmax (softmax elided: argmax-invariant) -----------
// OUTPUT DTYPE IS FLOAT32: the registry coerces the argmax output to f32.
// Writing int bit patterns (0..63) into a float buffer yields denormals
// (~1e-44 == 0.0) -> ||out|| = 0 -> rel_err = 1.000000 exactly, which is the
// alias observed in every previous round. Store the index AS A FLOAT.
__global__ void __launch_bounds__(64)
fc_argmax_k(const float* __restrict__ fcw, const float* __restrict__ fcb,
            float* __restrict__ out, int t)
{
    __shared__ float sh[Hh];
    const int n = blockIdx.x;
    const int tid = threadIdx.x;                 // 64 threads = 64 logits
    for (int i = tid; i < Hh; i += 64) sh[i] = g_h[n * Hh + i];
    __syncthreads();

    float acc = fcb[tid];
#pragma unroll 16
    for (int k = 0; k < Hh; k++) acc += sh[k] * fcw[k * Ee + tid];

    float v = acc; int bi = tid;
#pragma unroll
    for (int off = 16; off; off >>= 1) {
        float ov = __shfl_down_sync(0xffffffffu, v, off);
        int   oi = __shfl_down_sync(0xffffffffu, bi, off);
        if (ov > v || (ov == v && oi < bi)) { v = ov; bi = oi; }
    }
    __shared__ float wv[2];
    __shared__ int   wi[2];
    if ((tid & 31) == 0) { wv[tid >> 5] = v; wi[tid >> 5] = bi; }
    __syncthreads();
    if (tid == 0) {
        int r = wi[0];
        if (wv[1] > wv[0] || (wv[1] == wv[0] && wi[1] < wi[0])) r = wi[1];
        out[n * Tt + t] = (float)r;              // (N, T, 1), float32 value
    }
}

__global__ void __launch_bounds__(256)
zero_h_k()
{
    const int i = blockIdx.x * blockDim.x + threadIdx.x;
    g_h[i] = 0.f;
}

// ---------------- launch --------------------------------------------------
extern "C" void kernel_launch(void* const* d_in, const int* in_sizes, int n_in,
                              void* d_out, int out_size)
{
    float* out = (float*)d_out;

    // Identify inputs by element count; fall back to positional metadata
    // order (x, adj, Wz, bz, Wr, br, Wh, bh, fc_w, fc_b) if that fails.
    const float *x = 0, *adj = 0, *Wz = 0, *Wr = 0, *Wh = 0;
    const float *bz = 0, *br = 0, *bh = 0, *fcw = 0, *fcb = 0;
    for (int i = 0; i < n_in; i++) {
        const int s = in_sizes[i];
        const float* p = (const float*)d_in[i];
        if      (s == Nn * Tt * Dd) x = p;
        else if (s == Nn * Nn)      adj = p;
        else if (s == DH * Hh)      { if (!Wz) Wz = p; else if (!Wr) Wr = p; else Wh = p; }
        else if (s == Hh)           { if (!bz) bz = p; else if (!br) br = p; else bh = p; }
        else if (s == Hh * Ee)      fcw = p;
        else if (s == Ee)           fcb = p;
    }
    if ((!x || !adj || !Wz || !Wr || !Wh || !bz || !br || !bh || !fcw || !fcb)
        && n_in >= 10) {
        x   = (const float*)d_in[0];
        adj = (const float*)d_in[1];
        Wz  = (const float*)d_in[2];  bz = (const float*)d_in[3];
        Wr  = (const float*)d_in[4];  br = (const float*)d_in[5];
        Wh  = (const float*)d_in[6];  bh = (const float*)d_in[7];
        fcw = (const float*)d_in[8];  fcb = (const float*)d_in[9];
    }

    const dim3 tb(32, 32);

    // ---- fold weights with adj (associativity): W' = W @ adj, 1280 rows
    fold_k<0><<<dim3(32, 40), tb>>>(Wz, adj);
    fold_k<1><<<dim3(32, 40), tb>>>(Wr, adj);
    fold_k<2><<<dim3(32, 40), tb>>>(Wh, adj);

    // ---- pack [bz|br], h0 = 0
    pack_bias_k<<<(2 * Hh) / 256, 256>>>(bz, br);
    zero_h_k<<<(Nn * Hh) / 256, 256>>>();

    // ---- recurrent loop
    for (int t = 0; t < Tt; t++) {
        step_k<0><<<dim3(64, 32), tb>>>(x, t, (const float*)0);  // z and r*h
        step_k<1><<<dim3(32, 32), tb>>>(x, t, bh);               // cand + h update
        fc_argmax_k<<<Nn, 64>>>(fcw, fcb, out, t);               // logits + argmax
    }
}

// round 12
// speedup vs baseline: 2.2519x; 2.2519x over previous
#include <cuda_runtime.h>

// Problem constants
#define Nn 1024   // nodes (== hidden_dim)
#define Tt 32     // seq len
#define Dd 256    // state dim
#define Hh 1024   // hidden dim
#define Ee 64     // action logits
#define DH (Dd + Hh)   // 1280

// ---------------- scratch: __device__ globals, referenced ONLY from kernels
__device__ float g_WZR[DH * 2 * Hh];   // [Wz@adj | Wr@adj]  (1280 x 2048)
__device__ float g_WC [DH * Hh];       // Wh@adj             (1280 x 1024)
__device__ float g_h  [Nn * Hh];       // hidden state h_t
__device__ float g_z  [Nn * Hh];       // update gate z
__device__ float g_rh [Nn * Hh];       // r * h

__device__ __forceinline__ float sigm(float x) { return 1.0f / (1.0f + expf(-x)); }

// ---------------- 128x128x8 register-tiled SGEMM core ----------------------
// 256 threads, 8x8 accumulators each. A loaded K-major into As[k][m].
// ---------------- fold: dst = W[1280,1024] @ adj[1024,1024] ----------------
// DST 0: g_WZR cols [0,1024) (ldc 2048) | DST 1: g_WZR cols [1024,2048)
// DST 2: g_WC (ldc 1024)
template <int DST>
__global__ void __launch_bounds__(256)
fold_k(const float* __restrict__ A, const float* __restrict__ B)
{
    constexpr int BK = 8, TM = 8, TN = 8;
    __shared__ float As[BK][128];
    __shared__ float Bs[BK][128];
    const int tid  = threadIdx.x;
    const int trow = (tid >> 4) * TM;
    const int tcol = (tid & 15) * TN;
    const int aRow = tid >> 1;
    const int aCol = (tid & 1) * 4;
    const int bRow = tid >> 5;
    const int bCol = (tid & 31) * 4;

    const float* Ab = A + blockIdx.y * 128 * Hh;   // lda = 1024
    const float* Bb = B + blockIdx.x * 128;        // ldb = 1024

    float acc[TM][TN];
#pragma unroll
    for (int i = 0; i < TM; i++)
#pragma unroll
        for (int j = 0; j < TN; j++) acc[i][j] = 0.f;

    for (int k0 = 0; k0 < Hh; k0 += BK) {
        float4 av = *(const float4*)(Ab + aRow * Hh + k0 + aCol);
        As[aCol + 0][aRow] = av.x;
        As[aCol + 1][aRow] = av.y;
        As[aCol + 2][aRow] = av.z;
        As[aCol + 3][aRow] = av.w;
        *(float4*)(&Bs[bRow][bCol]) = *(const float4*)(Bb + (k0 + bRow) * Nn + bCol);
        __syncthreads();
#pragma unroll
        for (int kk = 0; kk < BK; kk++) {
            float ra[TM], rb[TN];
#pragma unroll
            for (int i = 0; i < TM; i++) ra[i] = As[kk][trow + i];
#pragma unroll
            for (int j = 0; j < TN; j++) rb[j] = Bs[kk][tcol + j];
#pragma unroll
            for (int i = 0; i < TM; i++)
#pragma unroll
                for (int j = 0; j < TN; j++) acc[i][j] += ra[i] * rb[j];
        }
        __syncthreads();
    }
    const int row0 = blockIdx.y * 128 + trow;
    const int col0 = blockIdx.x * 128 + tcol;
#pragma unroll
    for (int i = 0; i < TM; i++) {
#pragma unroll
        for (int j = 0; j < TN; j++) {
            const float v = acc[i][j];
            if (DST == 0)      g_WZR[(row0 + i) * 2 * Hh + col0 + j]      = v;
            else if (DST == 1) g_WZR[(row0 + i) * 2 * Hh + Hh + col0 + j] = v;
            else               g_WC [(row0 + i) * Hh + col0 + j]          = v;
        }
    }
}

// ---------------- recurrent step GEMMs, A = [x_t | state], K = 1280 --------
// EPI 0 (gates): B = g_WZR (ldb 2048), state = g_h
//    col <  H:  g_z [row,col]   = sigmoid(acc + bz[col])
//    col >= H:  g_rh[row,col-H] = sigmoid(acc + br[col-H]) * g_h[row,col-H]
// EPI 1 (cand):  B = g_WC (ldb 1024), state = g_rh
//    g_h = sigmoid(z*h + (1-z)*tanh(acc + bh[col]))
template <int EPI>
__global__ void __launch_bounds__(256)
step_k(const float* __restrict__ x, int t,
       const float* __restrict__ bias0, const float* __restrict__ bias1)
{
    constexpr int BK = 8, TM = 8, TN = 8;
    __shared__ float As[BK][128];
    __shared__ float Bs[BK][128];
    const int tid  = threadIdx.x;
    const int trow = (tid >> 4) * TM;
    const int tcol = (tid & 15) * TN;
    const int aRow = tid >> 1;
    const int aCol = (tid & 1) * 4;
    const int bRow = tid >> 5;
    const int bCol = (tid & 31) * 4;

    const int gRow   = blockIdx.y * 128 + aRow;
    const float* state = (EPI == 0) ? g_h : g_rh;
    const float* Wb    = (EPI == 0) ? g_WZR : g_WC;
    const int    ldb   = (EPI == 0) ? 2 * Hh : Hh;
    const int colBase  = blockIdx.x * 128;

    float acc[TM][TN];
#pragma unroll
    for (int i = 0; i < TM; i++)
#pragma unroll
        for (int j = 0; j < TN; j++) acc[i][j] = 0.f;

    for (int k0 = 0; k0 < DH; k0 += BK) {
        // Dd=256 is a multiple of BK=8, so each 8-wide K-slice lies wholly
        // in x (k0 < Dd) or wholly in the state (k0 >= Dd).
        const float* asrc = (k0 < Dd)
            ? (x + gRow * (Tt * Dd) + t * Dd + k0 + aCol)
            : (state + gRow * Hh + (k0 - Dd) + aCol);
        float4 av = *(const float4*)asrc;
        As[aCol + 0][aRow] = av.x;
        As[aCol + 1][aRow] = av.y;
        As[aCol + 2][aRow] = av.z;
        As[aCol + 3][aRow] = av.w;
        *(float4*)(&Bs[bRow][bCol]) =
            *(const float4*)(Wb + (k0 + bRow) * ldb + colBase + bCol);
        __syncthreads();
#pragma unroll
        for (int kk = 0; kk < BK; kk++) {
            float ra[TM], rb[TN];
#pragma unroll
            for (int i = 0; i < TM; i++) ra[i] = As[kk][trow + i];
#pragma unroll
            for (int j = 0; j < TN; j++) rb[j] = Bs[kk][tcol + j];
#pragma unroll
            for (int i = 0; i < TM; i++)
#pragma unroll
                for (int j = 0; j < TN; j++) acc[i][j] += ra[i] * rb[j];
        }
        __syncthreads();
    }

    const int row0 = blockIdx.y * 128 + trow;
    const int col0 = colBase + tcol;

    if (EPI == 0) {
        const bool zside = colBase < Hh;   // 128-wide block entirely on one side
#pragma unroll
        for (int i = 0; i < TM; i++) {
#pragma unroll
            for (int j = 0; j < TN; j++) {
                if (zside) {
                    const int idx = (row0 + i) * Hh + col0 + j;
                    g_z[idx] = sigm(acc[i][j] + bias0[col0 + j]);
                } else {
                    const int c = col0 - Hh + j;
                    const int idx = (row0 + i) * Hh + c;
                    g_rh[idx] = g_h[idx] * sigm(acc[i][j] + bias1[c]);
                }
            }
        }
    } else {
#pragma unroll
        for (int i = 0; i < TM; i++) {
#pragma unroll
            for (int j = 0; j < TN; j++) {
                const int idx = (row0 + i) * Hh + col0 + j;
                const float ht = tanhf(acc[i][j] + bias0[col0 + j]);
                const float z  = g_z[idx];
                const float h  = g_h[idx];
                g_h[idx] = sigm(z * h + (1.0f - z) * ht);
            }
        }
    }
}

// ---------------- fc + argmax (softmax elided; OUTPUT IS FLOAT32) ----------
__global__ void __launch_bounds__(64)
fc_argmax_k(const float* __restrict__ fcw, const float* __restrict__ fcb,
            float* __restrict__ out, int t)
{
    __shared__ float sh[Hh];
    const int n = blockIdx.x;
    const int tid = threadIdx.x;                 // 64 threads = 64 logits
    for (int i = tid; i < Hh; i += 64) sh[i] = g_h[n * Hh + i];
    __syncthreads();

    float acc = fcb[tid];
#pragma unroll 16
    for (int k = 0; k < Hh; k++) acc += sh[k] * fcw[k * Ee + tid];

    float v = acc; int bi = tid;
#pragma unroll
    for (int off = 16; off; off >>= 1) {
        float ov = __shfl_down_sync(0xffffffffu, v, off);
        int   oi = __shfl_down_sync(0xffffffffu, bi, off);
        if (ov > v || (ov == v && oi < bi)) { v = ov; bi = oi; }
    }
    __shared__ float wv[2];
    __shared__ int   wi[2];
    if ((tid & 31) == 0) { wv[tid >> 5] = v; wi[tid >> 5] = bi; }
    __syncthreads();
    if (tid == 0) {
        int r = wi[0];
        if (wv[1] > wv[0] || (wv[1] == wv[0] && wi[1] < wi[0])) r = wi[1];
        out[n * Tt + t] = (float)r;              // (N, T, 1), float32 value
    }
}

__global__ void __launch_bounds__(256)
zero_h_k()
{
    const int i = blockIdx.x * blockDim.x + threadIdx.x;
    g_h[i] = 0.f;
}

// ---------------- launch --------------------------------------------------
extern "C" void kernel_launch(void* const* d_in, const int* in_sizes, int n_in,
                              void* d_out, int out_size)
{
    float* out = (float*)d_out;

    // Identify inputs by element count; fall back to positional metadata
    // order (x, adj, Wz, bz, Wr, br, Wh, bh, fc_w, fc_b) if that fails.
    const float *x = 0, *adj = 0, *Wz = 0, *Wr = 0, *Wh = 0;
    const float *bz = 0, *br = 0, *bh = 0, *fcw = 0, *fcb = 0;
    for (int i = 0; i < n_in; i++) {
        const int s = in_sizes[i];
        const float* p = (const float*)d_in[i];
        if      (s == Nn * Tt * Dd) x = p;
        else if (s == Nn * Nn)      adj = p;
        else if (s == DH * Hh)      { if (!Wz) Wz = p; else if (!Wr) Wr = p; else Wh = p; }
        else if (s == Hh)           { if (!bz) bz = p; else if (!br) br = p; else bh = p; }
        else if (s == Hh * Ee)      fcw = p;
        else if (s == Ee)           fcb = p;
    }
    if ((!x || !adj || !Wz || !Wr || !Wh || !bz || !br || !bh || !fcw || !fcb)
        && n_in >= 10) {
        x   = (const float*)d_in[0];
        adj = (const float*)d_in[1];
        Wz  = (const float*)d_in[2];  bz = (const float*)d_in[3];
        Wr  = (const float*)d_in[4];  br = (const float*)d_in[5];
        Wh  = (const float*)d_in[6];  bh = (const float*)d_in[7];
        fcw = (const float*)d_in[8];  fcb = (const float*)d_in[9];
    }

    const dim3 blk(256);

    // ---- fold weights with adj (associativity): W' = W @ adj, 1280 rows
    fold_k<0><<<dim3(8, 10), blk>>>(Wz, adj);
    fold_k<1><<<dim3(8, 10), blk>>>(Wr, adj);
    fold_k<2><<<dim3(8, 10), blk>>>(Wh, adj);

    // ---- h0 = 0
    zero_h_k<<<(Nn * Hh) / 256, 256>>>();

    // ---- recurrent loop
    for (int t = 0; t < Tt; t++) {
        step_k<0><<<dim3(16, 8), blk>>>(x, t, bz, br);   // z and r*h
        step_k<1><<<dim3(8, 8),  blk>>>(x, t, bh, 0);    // cand + h update
        fc_argmax_k<<<Nn, 64>>>(fcw, fcb, out, t);       // logits + argmax
    }
}

// round 13
// speedup vs baseline: 3.2136x; 1.4271x over previous
#include <cuda_runtime.h>

// Problem constants
#define Nn 1024   // nodes (== hidden_dim)
#define Tt 32     // seq len
#define Dd 256    // state dim
#define Hh 1024   // hidden dim
#define Ee 64     // action logits
#define DH (Dd + Hh)   // 1280
#define BK 8

// ---------------- scratch: __device__ globals, referenced ONLY from kernels
__device__ float g_WZR[DH * 2 * Hh];        // [Wz@adj | Wr@adj] (1280 x 2048)
__device__ float g_WC [DH * Hh];            // Wh@adj            (1280 x 1024)
__device__ float g_Bzr[Tt * Nn * 2 * Hh];   // x@Wx'+bias (gates), per t  256MB
__device__ float g_Bc [Tt * Nn * Hh];       // x@Wx'+bias (cand),  per t  128MB
__device__ float g_h  [Nn * Hh];            // hidden state
__device__ float g_z  [Nn * Hh];            // update gate
__device__ float g_rh [Nn * Hh];            // r * h

__device__ __forceinline__ float sigm(float x) { return 1.0f / (1.0f + expf(-x)); }

// ---------------- shared double-buffered GEMM core -------------------------
// 256 threads, BMxBN tile, TM=BM/16 x TN=BN/16 accumulators per thread.
template <int BM, int BN>
__device__ __forceinline__ void mm_tile(const float (*Asb)[BM], const float (*Bsb)[BN],
                                        int trow, int tcol, float (*acc)[BN / 16])
{
    constexpr int TM = BM / 16, TN = BN / 16;
#pragma unroll
    for (int kk = 0; kk < BK; kk++) {
        float ra[TM], rb[TN];
#pragma unroll
        for (int i = 0; i < TM; i++) ra[i] = Asb[kk][trow + i];
#pragma unroll
        for (int j = 0; j < TN; j++) rb[j] = Bsb[kk][tcol + j];
#pragma unroll
        for (int i = 0; i < TM; i++)
#pragma unroll
            for (int j = 0; j < TN; j++) acc[i][j] += ra[i] * rb[j];
    }
}

template <int BM, int BN>
__device__ __forceinline__ void gemm_core(const float* __restrict__ A, int lda,
                                          const float* __restrict__ B, int ldb, int K,
                                          float (*acc)[BN / 16],
                                          float (*As)[BK][BM], float (*Bs)[BK][BN])
{
    const int tid  = threadIdx.x;
    const int trow = (tid >> 4) * (BM / 16);
    const int tcol = (tid & 15) * (BN / 16);
    const int aRow = tid >> 1;                  // BM*BK/4 = 2*BM float4 loads
    const int aCol = (tid & 1) * 4;
    const int bRow = tid / (BN / 4);            // BK*BN/4 = 2*BN float4 loads
    const int bCol = (tid % (BN / 4)) * 4;
    const bool aAct = tid < 2 * BM;
    const bool bAct = tid < 2 * BN;

    float4 av, bv;
    if (aAct) {
        av = *(const float4*)(A + aRow * lda + aCol);
        As[0][aCol + 0][aRow] = av.x;  As[0][aCol + 1][aRow] = av.y;
        As[0][aCol + 2][aRow] = av.z;  As[0][aCol + 3][aRow] = av.w;
    }
    if (bAct) {
        bv = *(const float4*)(B + bRow * ldb + bCol);
        *(float4*)(&Bs[0][bRow][bCol]) = bv;
    }
    __syncthreads();

    int buf = 0;
    for (int k0 = BK; k0 < K; k0 += BK) {
        if (aAct) av = *(const float4*)(A + aRow * lda + k0 + aCol);
        if (bAct) bv = *(const float4*)(B + (k0 + bRow) * ldb + bCol);
        mm_tile<BM, BN>(As[buf], Bs[buf], trow, tcol, acc);   // overlap w/ loads
        if (aAct) {
            As[buf ^ 1][aCol + 0][aRow] = av.x;  As[buf ^ 1][aCol + 1][aRow] = av.y;
            As[buf ^ 1][aCol + 2][aRow] = av.z;  As[buf ^ 1][aCol + 3][aRow] = av.w;
        }
        if (bAct) *(float4*)(&Bs[buf ^ 1][bRow][bCol]) = bv;
        __syncthreads();
        buf ^= 1;
    }
    mm_tile<BM, BN>(As[buf], Bs[buf], trow, tcol, acc);
}

// ---------------- fold: W' = W @ adj, all 3 gates in one launch (z-dim) ----
__global__ void __launch_bounds__(256)
fold_k(const float* __restrict__ Wz, const float* __restrict__ Wr,
       const float* __restrict__ Wh, const float* __restrict__ adj)
{
    __shared__ float As[2][BK][128];
    __shared__ float Bs[2][BK][128];
    float acc[8][8] = {};
    const int zz = blockIdx.z;
    const float* W = (zz == 0) ? Wz : (zz == 1) ? Wr : Wh;
    gemm_core<128, 128>(W + blockIdx.y * 128 * Hh, Hh,
                        adj + blockIdx.x * 128, Nn, Hh, acc, As, Bs);
    const int row0 = blockIdx.y * 128 + (threadIdx.x >> 4) * 8;
    const int col0 = blockIdx.x * 128 + (threadIdx.x & 15) * 8;
#pragma unroll
    for (int i = 0; i < 8; i++)
#pragma unroll
        for (int j = 0; j < 8; j++) {
            const float v = acc[i][j];
            if (zz == 0)      g_WZR[(row0 + i) * 2 * Hh + col0 + j]      = v;
            else if (zz == 1) g_WZR[(row0 + i) * 2 * Hh + Hh + col0 + j] = v;
            else              g_WC [(row0 + i) * Hh + col0 + j]          = v;
        }
}

// ---------------- precompute x-path for ALL t (time-parallel) --------------
// A = x as plain (N*T) x 256 matrix (row m = n*32+t at offset m*256).
// WHICH 0: Bzr[t,n,:] = x@WZR[0:256,:] + [bz|br]   (N=2048)
// WHICH 1: Bc [t,n,:] = x@WC [0:256,:] + bh        (N=1024)
template <int WHICH>
__global__ void __launch_bounds__(256)
pre_k(const float* __restrict__ x, const float* __restrict__ b0,
      const float* __restrict__ b1)
{
    __shared__ float As[2][BK][128];
    __shared__ float Bs[2][BK][128];
    float acc[8][8] = {};
    const float* B = ((WHICH == 0) ? &g_WZR[0] : &g_WC[0]) + blockIdx.x * 128;
    const int ldb = (WHICH == 0) ? 2 * Hh : Hh;
    gemm_core<128, 128>(x + blockIdx.y * 128 * Dd, Dd, B, ldb, Dd, acc, As, Bs);
    const int row0 = blockIdx.y * 128 + (threadIdx.x >> 4) * 8;
    const int col0 = blockIdx.x * 128 + (threadIdx.x & 15) * 8;
#pragma unroll
    for (int i = 0; i < 8; i++) {
        const int m = row0 + i, n = m >> 5, tt = m & 31;
#pragma unroll
        for (int j = 0; j < 8; j++) {
            const int col = col0 + j;
            if (WHICH == 0) {
                const float bias = (col < Hh) ? b0[col] : b1[col - Hh];
                g_Bzr[(tt * Nn + n) * 2 * Hh + col] = acc[i][j] + bias;
            } else {
                g_Bc[(tt * Nn + n) * Hh + col] = acc[i][j] + b0[col];
            }
        }
    }
}

// ---------------- serial gates: [z|r] = h @ WZR[256:,:], K=1024 ------------
__global__ void __launch_bounds__(256)
gates_k(int t)
{
    __shared__ float As[2][BK][128];
    __shared__ float Bs[2][BK][128];
    float acc[8][8] = {};
    gemm_core<128, 128>(&g_h[0] + blockIdx.y * 128 * Hh, Hh,
                        &g_WZR[0] + Dd * 2 * Hh + blockIdx.x * 128, 2 * Hh,
                        Hh, acc, As, Bs);
    const int row0 = blockIdx.y * 128 + (threadIdx.x >> 4) * 8;
    const int col0 = blockIdx.x * 128 + (threadIdx.x & 15) * 8;
    const float* P = &g_Bzr[0] + t * Nn * 2 * Hh;
    const bool zside = (blockIdx.x * 128) < Hh;     // block entirely on one side
#pragma unroll
    for (int i = 0; i < 8; i++) {
        const int row = row0 + i;
#pragma unroll
        for (int j = 0; j < 8; j++) {
            const int col = col0 + j;
            const float v = acc[i][j] + P[row * 2 * Hh + col];
            if (zside) {
                g_z[row * Hh + col] = sigm(v);
            } else {
                const int c = col - Hh;
                g_rh[row * Hh + c] = g_h[row * Hh + c] * sigm(v);
            }
        }
    }
}

// ---------------- serial candidate + GRU update, 64x128 tiles (128 CTAs) ---
__global__ void __launch_bounds__(256)
cand_k(int t)
{
    __shared__ float As[2][BK][64];
    __shared__ float Bs[2][BK][128];
    float acc[4][8] = {};
    gemm_core<64, 128>(&g_rh[0] + blockIdx.y * 64 * Hh, Hh,
                       &g_WC[0] + Dd * Hh + blockIdx.x * 128, Hh,
                       Hh, acc, As, Bs);
    const int row0 = blockIdx.y * 64 + (threadIdx.x >> 4) * 4;
    const int col0 = blockIdx.x * 128 + (threadIdx.x & 15) * 8;
    const float* P = &g_Bc[0] + t * Nn * Hh;
#pragma unroll
    for (int i = 0; i < 4; i++) {
#pragma unroll
        for (int j = 0; j < 8; j++) {
            const int idx = (row0 + i) * Hh + col0 + j;
            const float ht = tanhf(acc[i][j] + P[idx]);
            const float z  = g_z[idx];
            const float h  = g_h[idx];
            g_h[idx] = sigm(z * h + (1.0f - z) * ht);
        }
    }
}

// ---------------- t=0 degenerate step (h0 = 0 => GEMMs vanish) -------------
__global__ void __launch_bounds__(256)
step0_k()
{
    const int idx = blockIdx.x * blockDim.x + threadIdx.x;  // [0, N*H)
    const int n = idx >> 10, c = idx & 1023;
    const float z  = sigm(g_Bzr[n * 2 * Hh + c]);           // t=0, z half
    const float ht = tanhf(g_Bc[idx]);                      // t=0
    g_h[idx] = sigm((1.0f - z) * ht);
}

// ---------------- fc + argmax (softmax elided; OUTPUT IS FLOAT32) ----------
__global__ void __launch_bounds__(64)
fc_argmax_k(const float* __restrict__ fcw, const float* __restrict__ fcb,
            float* __restrict__ out, int t)
{
    __shared__ float sh[Hh];
    const int n = blockIdx.x;
    const int tid = threadIdx.x;                 // 64 threads = 64 logits
    for (int i = tid; i < Hh; i += 64) sh[i] = g_h[n * Hh + i];
    __syncthreads();

    float acc = fcb[tid];
#pragma unroll 16
    for (int k = 0; k < Hh; k++) acc += sh[k] * fcw[k * Ee + tid];

    float v = acc; int bi = tid;
#pragma unroll
    for (int off = 16; off; off >>= 1) {
        float ov = __shfl_down_sync(0xffffffffu, v, off);
        int   oi = __shfl_down_sync(0xffffffffu, bi, off);
        if (ov > v || (ov == v && oi < bi)) { v = ov; bi = oi; }
    }
    __shared__ float wv[2];
    __shared__ int   wi[2];
    if ((tid & 31) == 0) { wv[tid >> 5] = v; wi[tid >> 5] = bi; }
    __syncthreads();
    if (tid == 0) {
        int r = wi[0];
        if (wv[1] > wv[0] || (wv[1] == wv[0] && wi[1] < wi[0])) r = wi[1];
        out[n * Tt + t] = (float)r;              // (N, T, 1), float32 value
    }
}

// ---------------- launch --------------------------------------------------
extern "C" void kernel_launch(void* const* d_in, const int* in_sizes, int n_in,
                              void* d_out, int out_size)
{
    float* out = (float*)d_out;

    // Identify inputs by element count; fall back to positional order.
    const float *x = 0, *adj = 0, *Wz = 0, *Wr = 0, *Wh = 0;
    const float *bz = 0, *br = 0, *bh = 0, *fcw = 0, *fcb = 0;
    for (int i = 0; i < n_in; i++) {
        const int s = in_sizes[i];
        const float* p = (const float*)d_in[i];
        if      (s == Nn * Tt * Dd) x = p;
        else if (s == Nn * Nn)      adj = p;
        else if (s == DH * Hh)      { if (!Wz) Wz = p; else if (!Wr) Wr = p; else Wh = p; }
        else if (s == Hh)           { if (!bz) bz = p; else if (!br) br = p; else bh = p; }
        else if (s == Hh * Ee)      fcw = p;
        else if (s == Ee)           fcb = p;
    }
    if ((!x || !adj || !Wz || !Wr || !Wh || !bz || !br || !bh || !fcw || !fcb)
        && n_in >= 10) {
        x   = (const float*)d_in[0];
        adj = (const float*)d_in[1];
        Wz  = (const float*)d_in[2];  bz = (const float*)d_in[3];
        Wr  = (const float*)d_in[4];  br = (const float*)d_in[5];
        Wh  = (const float*)d_in[6];  bh = (const float*)d_in[7];
        fcw = (const float*)d_in[8];  fcb = (const float*)d_in[9];
    }

    // ---- fold all three W@adj in one launch (240 CTAs)
    fold_k<<<dim3(8, 10, 3), 256>>>(Wz, Wr, Wh, adj);

    // ---- time-parallel x-path precompute (4096 / 2048 CTAs, full machine)
    pre_k<0><<<dim3(16, 256), 256>>>(x, bz, br);
    pre_k<1><<<dim3(8, 256), 256>>>(x, bh, 0);

    // ---- t = 0 (h0 = 0: GEMMs degenerate to elementwise)
    step0_k<<<(Nn * Hh) / 256, 256>>>();
    fc_argmax_k<<<Nn, 64>>>(fcw, fcb, out, 0);

    // ---- recurrent loop, K = 1024 (x-part hoisted out)
    for (int t = 1; t < Tt; t++) {
        gates_k<<<dim3(16, 8), 256>>>(t);    // z and r*h   (128 CTAs)
        cand_k<<<dim3(8, 16), 256>>>(t);     // h update    (128 CTAs)
        fc_argmax_k<<<Nn, 64>>>(fcw, fcb, out, t);
    }
}